// round 14
// baseline (speedup 1.0000x reference)
#include <cuda_runtime.h>
#include <cstdint>

// ---------------------------------------------------------------------------
// UniformAssigner — flat chassis, 4 launches, round-trip-free k_main.
//  k_main  : 1 anchor/thread; branch-free sweep (4x u32 masks). Epilogue
//            computes exact reference IoU and APPENDS candidates to 3
//            thread-private slots (pure STG, no atomics / no .cg loads).
//            Overflow >3 (P~0.4%) falls back to direct cascade.
//  k_drain : each thread s3-filters + cascades its own <=3 candidates into
//            the per-gt top-4 (lock-free atomicMax cascade); 200K independent
//            chains -> latency hidden by TLP.
//  k_scatter: <=512 entries -> atomicMax gt_id onto assigned[anchor].
//  k_final : labels + bboxes; block 0 re-zeroes g_topk for the next replay.
// ---------------------------------------------------------------------------

#define MAXM   128
#define MAXN   (1u << 20)
#define K_CAND 3
typedef unsigned long long ull;

__device__ ull           g_topk[MAXM * 4];     // packed (iou<<32|idx), 0=empty
__device__ int           g_assigned[MAXN];     // baseline 0/-1, then gt ids
__device__ ull           g_ckey[MAXN * K_CAND];// (iou_bits<<32 | g)
__device__ unsigned char g_ccnt[MAXN];

// lock-free top-4 insert; slots monotone non-decreasing, pairwise sorted.
__device__ __forceinline__ void cascade(ull* slots, ull key) {
#pragma unroll
    for (int s = 0; s < 4; s++) {
        ull prev = atomicMax(&slots[s], key);
        if (prev == 0ULL) break;        // landed in an empty slot
        key = prev < key ? prev : key;  // push displaced smaller key down
    }
}

// ---------------------------------------------------------------- main ------
__global__ void __launch_bounds__(256)
k_main(const float4* __restrict__ anchors, const float4* __restrict__ gts,
       int N, int M) {
    __shared__ float4 sbox[MAXM];
    __shared__ float  sarea[MAXM];   // exact gt area (epilogue / union)
    __shared__ float  sthr[MAXM];    // 0.12 * gt area (conservative gate)
    for (int g = threadIdx.x; g < M; g += blockDim.x) {
        float4 b  = gts[g];
        float  ar = (b.z - b.x) * (b.w - b.y);
        sbox[g]  = b;
        sarea[g] = ar;
        sthr[g]  = 0.12f * ar;
    }
    __syncthreads();

    const int i = blockIdx.x * blockDim.x + threadIdx.x;
    if (i >= N) return;

    const float4 a     = anchors[i];
    const float  areaA = (a.z - a.x) * (a.w - a.y);
    const float  tA    = 0.12f * areaA;

    // ---- branch-free sweep: 4x u32 masks, IMAD accumulation --------------
    // gate: max(iw,0)*ih >= tA + thr.  thr >= 0.12*128 > 0, single clamp
    // kills the (-)*(-) false positive; true candidates never dropped.
    unsigned msk[4];
#pragma unroll
    for (int w = 0; w < 4; w++) {
        int base = w * 32;
        unsigned m = 0;
        if (base < M) {
            int lim = M - base;
            if (lim > 32) lim = 32;
#pragma unroll 4
            for (int j = 0; j < lim; j++) {
                float4 b   = sbox[base + j];
                float  thr = sthr[base + j];
                float iw = fminf(a.z, b.z) - fmaxf(a.x, b.x);
                float ih = fminf(a.w, b.w) - fmaxf(a.y, b.y);
                float in = fmaxf(iw, 0.0f) * ih;
                m = m * 2u + (unsigned)(in >= tA + thr);   // IMAD
            }
            if (lim < 32) m <<= (32 - lim);  // bit(31-j) <-> g=base+j
        }
        msk[w] = m;
    }

    // ---- epilogue: exact math, fire-and-forget private-slot appends ------
    int ign = 0, cnt = 0;
#pragma unroll
    for (int w = 0; w < 4; w++) {
        int base = w * 32;
        unsigned m = msk[w];
        while (m) {
            int j = __clz(m);
            m &= ~(0x80000000u >> j);
            int g = base + j;
            float4 b = sbox[g];
            float iw    = fminf(a.z, b.z) - fmaxf(a.x, b.x);
            float ih    = fminf(a.w, b.w) - fmaxf(a.y, b.y);
            float inter = fmaxf(iw, 0.0f) * fmaxf(ih, 0.0f);
            float uni   = (areaA + sarea[g]) - inter;
            float iou   = inter / fmaxf(uni, 1e-7f);   // exact ref expression
            ign |= (iou >= 0.7f);
            if (iou >= 0.15f) {
                if (cnt < K_CAND) {          // pure store, no round-trip
                    g_ckey[i * K_CAND + cnt] =
                        ((ull)__float_as_uint(iou) << 32) | (unsigned)g;
                    cnt++;
                } else {                     // rare overflow (~0.4% anchors)
                    cascade(&g_topk[g * 4],
                            ((ull)__float_as_uint(iou) << 32) | (unsigned)i);
                }
            }
        }
    }

    g_ccnt[i]     = (unsigned char)cnt;
    g_assigned[i] = ign ? -1 : 0;
}

// ---------------------------------------------------------------- drain -----
__global__ void __launch_bounds__(256)
k_drain(int N) {
    const int i = blockIdx.x * blockDim.x + threadIdx.x;
    if (i >= N) return;
    int cnt = g_ccnt[i];
#pragma unroll
    for (int c = 0; c < K_CAND; c++) {
        if (c >= cnt) break;
        ull e   = g_ckey[i * K_CAND + c];
        int g   = (int)(e & 0xffffffffULL);
        ull key = (e & 0xffffffff00000000ULL) | (unsigned)i;
        ull* slots = &g_topk[g * 4];
        // stale slot[3] read can only be <= current -> skip is safe.
        ull s3;
        asm volatile("ld.global.cg.u64 %0, [%1];" : "=l"(s3) : "l"(slots + 3));
        if (key > s3) cascade(slots, key);
    }
}

// ------------------------------------------------------------- scatter ------
__global__ void k_scatter(int M) {
    int i = blockIdx.x * blockDim.x + threadIdx.x;
    if (i >= M * 4) return;
    ull key = g_topk[i];
    if (key == 0ULL) return;
    float iou = __uint_as_float((unsigned)(key >> 32));
    if (iou >= 0.15f) {
        int idx = (int)(key & 0xffffffffULL);
        atomicMax(&g_assigned[idx], i / 4 + 1);
    }
}

// ------------------------------------------------------------ finalize ------
__global__ void __launch_bounds__(256)
k_final(const float4* __restrict__ gts, const int* __restrict__ labels,
        float* __restrict__ out, int N) {
    // block 0: re-zero g_topk for the next graph replay (scatter already ran;
    // nothing in this kernel reads g_topk).  g_ccnt is rewritten each run.
    if (blockIdx.x == 0) {
#pragma unroll
        for (int k = 0; k < 2; k++) g_topk[threadIdx.x + k * 256] = 0ULL;
    }

    const int i = blockIdx.x * blockDim.x + threadIdx.x;
    if (i >= N) return;
    int a = g_assigned[i];
    float  lab;
    float4 bb;
    if (a > 0) {
        lab = (float)labels[a - 1];
        bb  = gts[a - 1];
    } else {
        lab = (a == 0) ? 0.0f : -1.0f;
        bb  = make_float4(-1.0f, -1.0f, -1.0f, -1.0f);
    }
    out[i] = lab;
    if ((N & 3) == 0) {
        reinterpret_cast<float4*>(out + N)[i] = bb;   // out+N is 16B-aligned
    } else {
        float* p = out + N + 4 * i;
        p[0] = bb.x; p[1] = bb.y; p[2] = bb.z; p[3] = bb.w;
    }
}

// --------------------------------------------------------------------------
extern "C" void kernel_launch(void* const* d_in, const int* in_sizes, int n_in,
                              void* d_out, int out_size) {
    const float4* anchors = (const float4*)d_in[0];
    const float4* gts     = (const float4*)d_in[1];
    const int*    labels  = (const int*)d_in[2];
    int N = in_sizes[0] / 4;
    int M = in_sizes[1] / 4;
    float* out = (float*)d_out;

    int nb = (N + 255) / 256;
    k_main<<<nb, 256>>>(anchors, gts, N, M);
    k_drain<<<nb, 256>>>(N);
    k_scatter<<<(M * 4 + 255) / 256, 256>>>(M);
    k_final<<<nb, 256>>>(gts, labels, out, N);
}

// round 15
// speedup vs baseline: 2.3158x; 2.3158x over previous
#include <cuda_runtime.h>
#include <cstdint>

// ---------------------------------------------------------------------------
// UniformAssigner — flat chassis, 3 launches, SMEM-staged top-4.
//  k_main  : 2 anchors/thread (391 blocks). Branch-free sweep (4x u32 masks).
//            Epilogue: exact reference IoU; candidates filter against the
//            BLOCK-level top-4 in shared memory (LDS + smem atomicMax cascade
//            -- no L2 round-trips).  Block end: merge <=512 block slots into
//            the global per-gt top-4 (independent .cg-filtered cascades,
//            spread in time across block retirements).
//  k_scatter: <=512 entries -> atomicMax gt_id onto assigned[anchor].
//  k_final : labels + bboxes; block 0 re-zeroes g_topk for the next replay.
// ---------------------------------------------------------------------------

#define MAXM 128
#define MAXN (1u << 20)
typedef unsigned long long ull;

__device__ ull g_topk[MAXM * 4];      // packed (iou_bits<<32|idx), 0 = empty
__device__ int g_assigned[MAXN];      // baseline 0/-1, then gt ids

// lock-free top-4 insert (global); slots monotone, pairwise sorted.
__device__ __forceinline__ void cascade_g(ull* slots, ull key) {
#pragma unroll
    for (int s = 0; s < 4; s++) {
        ull prev = atomicMax(&slots[s], key);
        if (prev == 0ULL) break;
        key = prev < key ? prev : key;
    }
}
// same algorithm on shared memory (ATOMS — in-SM, no L2).
__device__ __forceinline__ void cascade_s(ull* slots, ull key) {
#pragma unroll
    for (int s = 0; s < 4; s++) {
        ull prev = atomicMax(&slots[s], key);
        if (prev == 0ULL) break;
        key = prev < key ? prev : key;
    }
}

// ---------------------------------------------------------------- main ------
__global__ void __launch_bounds__(256)
k_main(const float4* __restrict__ anchors, const float4* __restrict__ gts,
       int N, int M) {
    __shared__ float4 sbox[MAXM];
    __shared__ float  sarea[MAXM];   // exact gt area (epilogue / union)
    __shared__ float  sthr[MAXM];    // 0.12 * gt area (conservative gate)
    __shared__ ull    stopk[MAXM * 4];
    for (int g = threadIdx.x; g < M; g += blockDim.x) {
        float4 b  = gts[g];
        float  ar = (b.z - b.x) * (b.w - b.y);
        sbox[g]  = b;
        sarea[g] = ar;
        sthr[g]  = 0.12f * ar;
    }
    for (int s = threadIdx.x; s < MAXM * 4; s += blockDim.x) stopk[s] = 0ULL;
    __syncthreads();

    const int T  = gridDim.x * blockDim.x;
    const int i0 = blockIdx.x * blockDim.x + threadIdx.x;
    const int i1 = i0 + T;

    // sentinel far-away boxes for out-of-range lanes (no early return:
    // all threads must reach the __syncthreads before the merge phase).
    float4 a0 = (i0 < N) ? anchors[i0] : make_float4(3e9f, 3e9f, 2e9f, 2e9f);
    float4 a1 = (i1 < N) ? anchors[i1] : make_float4(3e9f, 3e9f, 2e9f, 2e9f);
    const float areaA0 = (a0.z - a0.x) * (a0.w - a0.y);
    const float areaA1 = (a1.z - a1.x) * (a1.w - a1.y);
    const float tA0 = 0.12f * areaA0;
    const float tA1 = 0.12f * areaA1;

    // ---- branch-free sweep: 4x u32 masks per anchor, IMAD accumulation ---
    // gate: max(iw,0)*ih >= tA + thr.  thr >= 0.12*128 > 0; single clamp
    // kills the (-)*(-) false positive; true candidates never dropped.
    unsigned msk0[4], msk1[4];
#pragma unroll
    for (int w = 0; w < 4; w++) {
        int base = w * 32;
        unsigned m0 = 0, m1 = 0;
        if (base < M) {
            int lim = M - base;
            if (lim > 32) lim = 32;
#pragma unroll 4
            for (int j = 0; j < lim; j++) {
                float4 b   = sbox[base + j];
                float  thr = sthr[base + j];
                float iw0 = fminf(a0.z, b.z) - fmaxf(a0.x, b.x);
                float ih0 = fminf(a0.w, b.w) - fmaxf(a0.y, b.y);
                float in0 = fmaxf(iw0, 0.0f) * ih0;
                float iw1 = fminf(a1.z, b.z) - fmaxf(a1.x, b.x);
                float ih1 = fminf(a1.w, b.w) - fmaxf(a1.y, b.y);
                float in1 = fmaxf(iw1, 0.0f) * ih1;
                m0 = m0 * 2u + (unsigned)(in0 >= tA0 + thr);   // IMAD
                m1 = m1 * 2u + (unsigned)(in1 >= tA1 + thr);
            }
            if (lim < 32) { m0 <<= (32 - lim); m1 <<= (32 - lim); }
        }
        msk0[w] = m0;
        msk1[w] = m1;
    }

    // ---- epilogue: exact math; candidates -> BLOCK top-4 in smem ---------
    int ign0 = 0, ign1 = 0;
#pragma unroll
    for (int w = 0; w < 4; w++) {
        int base = w * 32;
        unsigned m = msk0[w];
        while (m) {
            int j = __clz(m);
            m &= ~(0x80000000u >> j);
            int g = base + j;
            float4 b = sbox[g];
            float iw    = fminf(a0.z, b.z) - fmaxf(a0.x, b.x);
            float ih    = fminf(a0.w, b.w) - fmaxf(a0.y, b.y);
            float inter = fmaxf(iw, 0.0f) * fmaxf(ih, 0.0f);
            float uni   = (areaA0 + sarea[g]) - inter;
            float iou   = inter / fmaxf(uni, 1e-7f);   // exact ref expression
            ign0 |= (iou >= 0.7f);
            if (iou >= 0.15f) {
                ull key = ((ull)__float_as_uint(iou) << 32) | (unsigned)i0;
                // stale smem slot[3] read only under-filters (monotone)
                if (key > stopk[g * 4 + 3]) cascade_s(&stopk[g * 4], key);
            }
        }
        m = msk1[w];
        while (m) {
            int j = __clz(m);
            m &= ~(0x80000000u >> j);
            int g = base + j;
            float4 b = sbox[g];
            float iw    = fminf(a1.z, b.z) - fmaxf(a1.x, b.x);
            float ih    = fminf(a1.w, b.w) - fmaxf(a1.y, b.y);
            float inter = fmaxf(iw, 0.0f) * fmaxf(ih, 0.0f);
            float uni   = (areaA1 + sarea[g]) - inter;
            float iou   = inter / fmaxf(uni, 1e-7f);
            ign1 |= (iou >= 0.7f);
            if (iou >= 0.15f) {
                ull key = ((ull)__float_as_uint(iou) << 32) | (unsigned)i1;
                if (key > stopk[g * 4 + 3]) cascade_s(&stopk[g * 4], key);
            }
        }
    }

    if (i0 < N) g_assigned[i0] = ign0 ? -1 : 0;
    if (i1 < N) g_assigned[i1] = ign1 ? -1 : 0;

    // ---- merge: block top-4 -> global top-4 ------------------------------
    // global top-4 of each gt is contained in the union of block top-4s,
    // so cascading every nonzero block slot is exact.  <=2 independent
    // slots/thread -> .cg filter loads overlap (MLP); merges of different
    // blocks are spread in time, keeping per-address atomic pressure low.
    __syncthreads();
    for (int s = threadIdx.x; s < M * 4; s += blockDim.x) {
        ull key = stopk[s];
        if (key == 0ULL) continue;
        int g = s >> 2;
        ull* slots = &g_topk[g * 4];
        ull s3;  // stale read only under-filters (slots monotone)
        asm volatile("ld.global.cg.u64 %0, [%1];" : "=l"(s3) : "l"(slots + 3));
        if (key > s3) cascade_g(slots, key);
    }
}

// ------------------------------------------------------------- scatter ------
__global__ void k_scatter(int M) {
    int i = blockIdx.x * blockDim.x + threadIdx.x;
    if (i >= M * 4) return;
    ull key = g_topk[i];
    if (key == 0ULL) return;
    float iou = __uint_as_float((unsigned)(key >> 32));
    if (iou >= 0.15f) {
        int idx = (int)(key & 0xffffffffULL);
        atomicMax(&g_assigned[idx], i / 4 + 1);
    }
}

// ------------------------------------------------------------ finalize ------
__global__ void __launch_bounds__(256)
k_final(const float4* __restrict__ gts, const int* __restrict__ labels,
        float* __restrict__ out, int N) {
    // block 0: re-zero g_topk for the next graph replay (scatter already ran;
    // nothing in this kernel reads g_topk).
    if (blockIdx.x == 0) {
#pragma unroll
        for (int k = 0; k < 2; k++) g_topk[threadIdx.x + k * 256] = 0ULL;
    }

    const int i = blockIdx.x * blockDim.x + threadIdx.x;
    if (i >= N) return;
    int a = g_assigned[i];
    float  lab;
    float4 bb;
    if (a > 0) {
        lab = (float)labels[a - 1];
        bb  = gts[a - 1];
    } else {
        lab = (a == 0) ? 0.0f : -1.0f;
        bb  = make_float4(-1.0f, -1.0f, -1.0f, -1.0f);
    }
    out[i] = lab;
    if ((N & 3) == 0) {
        reinterpret_cast<float4*>(out + N)[i] = bb;   // out+N is 16B-aligned
    } else {
        float* p = out + N + 4 * i;
        p[0] = bb.x; p[1] = bb.y; p[2] = bb.z; p[3] = bb.w;
    }
}

// --------------------------------------------------------------------------
extern "C" void kernel_launch(void* const* d_in, const int* in_sizes, int n_in,
                              void* d_out, int out_size) {
    const float4* anchors = (const float4*)d_in[0];
    const float4* gts     = (const float4*)d_in[1];
    const int*    labels  = (const int*)d_in[2];
    int N = in_sizes[0] / 4;
    int M = in_sizes[1] / 4;
    float* out = (float*)d_out;

    k_main<<<(N + 511) / 512, 256>>>(anchors, gts, N, M);   // 391 blocks
    k_scatter<<<(M * 4 + 255) / 256, 256>>>(M);
    k_final<<<(N + 255) / 256, 256>>>(gts, labels, out, N);
}

// round 17
// speedup vs baseline: 2.5717x; 1.1105x over previous
#include <cuda_runtime.h>
#include <cstdint>

// ---------------------------------------------------------------------------
// UniformAssigner — flat chassis, 3 launches, SMEM-staged top-4, ANC=1.
//  k_main  : 1 anchor/thread (782 blocks -> ~42 warps/SM). Branch-free sweep
//            (4x u32 masks, FFMA-folded gate). Epilogue: exact reference IoU;
//            candidates go to the BLOCK top-4 in shared memory (LDS filter +
//            smem atomicMax cascade -- no L2 round-trips). Block end: merge
//            nonzero block slots into global per-gt top-4 (s3-filtered).
//  k_scatter: <=512 entries -> atomicMax gt_id onto assigned[anchor].
//  k_final : labels + bboxes; block 0 re-zeroes g_topk for the next replay.
// ---------------------------------------------------------------------------

#define MAXM 128
#define MAXN (1u << 20)
typedef unsigned long long ull;

__device__ ull g_topk[MAXM * 4];      // packed (iou_bits<<32|idx), 0 = empty
__device__ int g_assigned[MAXN];      // baseline 0/-1, then gt ids

// lock-free top-4 insert; slots monotone non-decreasing, pairwise sorted.
__device__ __forceinline__ void cascade_g(ull* slots, ull key) {
#pragma unroll
    for (int s = 0; s < 4; s++) {
        ull prev = atomicMax(&slots[s], key);
        if (prev == 0ULL) break;
        key = prev < key ? prev : key;
    }
}
__device__ __forceinline__ void cascade_s(ull* slots, ull key) {
#pragma unroll
    for (int s = 0; s < 4; s++) {
        ull prev = atomicMax(&slots[s], key);   // ATOMS: in-SM, no L2
        if (prev == 0ULL) break;
        key = prev < key ? prev : key;
    }
}

// ---------------------------------------------------------------- main ------
__global__ void __launch_bounds__(256)
k_main(const float4* __restrict__ anchors, const float4* __restrict__ gts,
       int N, int M) {
    __shared__ float4 sbox[MAXM];
    __shared__ float  sarea[MAXM];   // exact gt area (epilogue / union)
    __shared__ float  sthr[MAXM];    // 0.12 * gt area (conservative gate)
    __shared__ ull    stopk[MAXM * 4];
    for (int g = threadIdx.x; g < M; g += blockDim.x) {
        float4 b  = gts[g];
        float  ar = (b.z - b.x) * (b.w - b.y);
        sbox[g]  = b;
        sarea[g] = ar;
        sthr[g]  = 0.12f * ar;
    }
    for (int s = threadIdx.x; s < MAXM * 4; s += blockDim.x) stopk[s] = 0ULL;
    __syncthreads();

    const int i = blockIdx.x * blockDim.x + threadIdx.x;
    // sentinel far-away box for tail lanes: no early return — every thread
    // must reach the merge-phase __syncthreads.
    const float4 a = (i < N) ? anchors[i]
                             : make_float4(3e9f, 3e9f, 2e9f, 2e9f);
    const float areaA = (a.z - a.x) * (a.w - a.y);
    const float tA    = 0.12f * areaA;

    // ---- branch-free sweep: 4x u32 masks, IMAD accumulation --------------
    // gate: fmaf(max(iw,0), ih, -thr) >= tA  (== max(iw,0)*ih >= tA+thr up
    // to 1 ulp, covered by the 0.12-vs-0.1304 conservativeness margin).
    // thr >= 0.12*128 > 0; single clamp kills the (-)*(-) false positive.
    unsigned msk[4];
#pragma unroll
    for (int w = 0; w < 4; w++) {
        int base = w * 32;
        unsigned m = 0;
        if (base < M) {
            int lim = M - base;
            if (lim > 32) lim = 32;
#pragma unroll 4
            for (int j = 0; j < lim; j++) {
                float4 b   = sbox[base + j];
                float  thr = sthr[base + j];
                float iw  = fminf(a.z, b.z) - fmaxf(a.x, b.x);
                float ih  = fminf(a.w, b.w) - fmaxf(a.y, b.y);
                float val = fmaf(fmaxf(iw, 0.0f), ih, -thr);
                m = m * 2u + (unsigned)(val >= tA);        // IMAD
            }
            if (lim < 32) m <<= (32 - lim);   // bit(31-j) <-> g=base+j
        }
        msk[w] = m;
    }

    // ---- epilogue: exact math; candidates -> BLOCK top-4 in smem ---------
    int ign = 0;
#pragma unroll
    for (int w = 0; w < 4; w++) {
        int base = w * 32;
        unsigned m = msk[w];
        while (m) {
            int j = __clz(m);
            m &= ~(0x80000000u >> j);
            int g = base + j;
            float4 b = sbox[g];
            float iw    = fminf(a.z, b.z) - fmaxf(a.x, b.x);
            float ih    = fminf(a.w, b.w) - fmaxf(a.y, b.y);
            float inter = fmaxf(iw, 0.0f) * fmaxf(ih, 0.0f);
            float uni   = (areaA + sarea[g]) - inter;
            float iou   = inter / fmaxf(uni, 1e-7f);   // exact ref expression
            ign |= (iou >= 0.7f);
            if (iou >= 0.15f) {
                ull key = ((ull)__float_as_uint(iou) << 32) | (unsigned)i;
                // stale smem slot[3] read only under-filters (monotone)
                if (key > stopk[g * 4 + 3]) cascade_s(&stopk[g * 4], key);
            }
        }
    }

    if (i < N) g_assigned[i] = ign ? -1 : 0;

    // ---- merge: block top-4 -> global top-4 ------------------------------
    // global top-4 of each gt is contained in the union of block top-4s, so
    // cascading every nonzero block slot is exact.  2 slots/thread, .cg
    // filter loads overlap (MLP); block retirements spread the atomics.
    __syncthreads();
    for (int s = threadIdx.x; s < M * 4; s += blockDim.x) {
        ull key = stopk[s];
        if (key == 0ULL) continue;
        int g = s >> 2;
        ull* slots = &g_topk[g * 4];
        ull s3;  // stale read only under-filters (slots monotone)
        asm volatile("ld.global.cg.u64 %0, [%1];" : "=l"(s3) : "l"(slots + 3));
        if (key > s3) cascade_g(slots, key);
    }
}

// ------------------------------------------------------------- scatter ------
__global__ void k_scatter(int M) {
    int i = blockIdx.x * blockDim.x + threadIdx.x;
    if (i >= M * 4) return;
    ull key = g_topk[i];
    if (key == 0ULL) return;
    float iou = __uint_as_float((unsigned)(key >> 32));
    if (iou >= 0.15f) {
        int idx = (int)(key & 0xffffffffULL);
        atomicMax(&g_assigned[idx], i / 4 + 1);
    }
}

// ------------------------------------------------------------ finalize ------
__global__ void __launch_bounds__(256)
k_final(const float4* __restrict__ gts, const int* __restrict__ labels,
        float* __restrict__ out, int N) {
    // block 0: re-zero g_topk for the next graph replay (scatter already ran;
    // nothing in this kernel reads g_topk).
    if (blockIdx.x == 0) {
#pragma unroll
        for (int k = 0; k < 2; k++) g_topk[threadIdx.x + k * 256] = 0ULL;
    }

    const int i = blockIdx.x * blockDim.x + threadIdx.x;
    if (i >= N) return;
    int a = g_assigned[i];
    float  lab;
    float4 bb;
    if (a > 0) {
        lab = (float)labels[a - 1];
        bb  = gts[a - 1];
    } else {
        lab = (a == 0) ? 0.0f : -1.0f;
        bb  = make_float4(-1.0f, -1.0f, -1.0f, -1.0f);
    }
    out[i] = lab;
    if ((N & 3) == 0) {
        reinterpret_cast<float4*>(out + N)[i] = bb;   // out+N is 16B-aligned
    } else {
        float* p = out + N + 4 * i;
        p[0] = bb.x; p[1] = bb.y; p[2] = bb.z; p[3] = bb.w;
    }
}

// --------------------------------------------------------------------------
extern "C" void kernel_launch(void* const* d_in, const int* in_sizes, int n_in,
                              void* d_out, int out_size) {
    const float4* anchors = (const float4*)d_in[0];
    const float4* gts     = (const float4*)d_in[1];
    const int*    labels  = (const int*)d_in[2];
    int N = in_sizes[0] / 4;
    int M = in_sizes[1] / 4;
    float* out = (float*)d_out;

    k_main<<<(N + 255) / 256, 256>>>(anchors, gts, N, M);   // 782 blocks
    k_scatter<<<(M * 4 + 255) / 256, 256>>>(M);
    k_final<<<(N + 255) / 256, 256>>>(gts, labels, out, N);
}